// round 6
// baseline (speedup 1.0000x reference)
#include <cuda_runtime.h>
#include <cuda_bf16.h>
#include <cstdint>
#include <math.h>

namespace {
constexpr int NTOK = 8192;
constexpr int D    = 1024;
constexpr int HD   = 512;
constexpr int NE   = 8;
constexpr int BM = 128, BN = 128;
constexpr int CAP  = 17408;            // 2*NTOK + per-expert pad to 128

// dynamic smem layout (bytes)
constexpr int OFF_ROW = 0;             // int[128]
constexpr int OFF_TOK = 512;           // int[128]
constexpr int OFF_W   = 1024;          // float[128]
constexpr int OFF_A   = 1536;
constexpr int A_HL    = 128 * 24 * 2;  // 6144  (one hi or lo buffer)
constexpr int A_ST    = 2 * A_HL;      // 12288 (per stage: hi+lo)
constexpr int OFF_B   = OFF_A + 4 * A_ST;   // 50688
constexpr int B_HL    = 16 * 136 * 2;  // 4352
constexpr int B_ST    = 2 * B_HL;      // 8704
constexpr int SMEM_BYTES = OFF_B + 4 * B_ST;  // 85504
}

__device__ int   g_counts[NE];
__device__ int   g_offsets[NE + 1];
__device__ int   g_cursor[NE];
__device__ int   g_perm[CAP];
__device__ float g_wgt[CAP];
__device__ int   g_tok_e[NTOK * 2];
__device__ float g_tok_w[NTOK * 2];

// split-bf16 operands, row-major (weights [K,N])
__device__ __align__(16) __nv_bfloat16 g_Xh[NTOK * D],  g_Xl[NTOK * D];
__device__ __align__(16) __nv_bfloat16 g_W1h[D * HD],  g_W1l[D * HD];
__device__ __align__(16) __nv_bfloat16 g_W2h[HD * D],  g_W2l[HD * D];
__device__ __align__(16) __nv_bfloat16 g_r1h[NE * D * HD], g_r1l[NE * D * HD];
__device__ __align__(16) __nv_bfloat16 g_r2h[NE * HD * D], g_r2l[NE * HD * D];
__device__ __align__(16) __nv_bfloat16 g_Hsh[NTOK * HD], g_Hsl[NTOK * HD];
__device__ __align__(16) __nv_bfloat16 g_Hrh[(size_t)CAP * HD], g_Hrl[(size_t)CAP * HD];

// ---------------- routing / bookkeeping ----------------

__global__ void init_kernel() {
    int i = blockIdx.x * blockDim.x + threadIdx.x;
    if (i < NE) g_counts[i] = 0;
    if (i < CAP) { g_perm[i] = 0; g_wgt[i] = 0.0f; }
}

__global__ void routing_kernel(const float* __restrict__ X,
                               const float* __restrict__ RW,
                               const float* __restrict__ EB) {
    int warp = (blockIdx.x * blockDim.x + threadIdx.x) >> 5;
    int lane = threadIdx.x & 31;
    if (warp >= NTOK) return;
    const float* x = X + (size_t)warp * D;
    float acc[NE];
#pragma unroll
    for (int e = 0; e < NE; e++) acc[e] = 0.0f;
    for (int k = lane; k < D; k += 32) {
        float xv = x[k];
#pragma unroll
        for (int e = 0; e < NE; e++) acc[e] = fmaf(xv, RW[e * D + k], acc[e]);
    }
#pragma unroll
    for (int e = 0; e < NE; e++) {
#pragma unroll
        for (int o = 16; o > 0; o >>= 1)
            acc[e] += __shfl_down_sync(0xffffffffu, acc[e], o);
    }
    if (lane == 0) {
        float act[NE];
#pragma unroll
        for (int e = 0; e < NE; e++) {
            float l = acc[e] + EB[e];
            float sp = (l > 0.0f) ? (l + log1pf(expf(-l))) : log1pf(expf(l));
            act[e] = sqrtf(sp);
        }
        int i0 = 0;
#pragma unroll
        for (int e = 1; e < NE; e++) if (act[e] > act[i0]) i0 = e;
        int i1 = (i0 == 0) ? 1 : 0;
#pragma unroll
        for (int e = 0; e < NE; e++)
            if (e != i0 && act[e] > act[i1]) i1 = e;
        g_tok_e[2 * warp + 0] = i0; g_tok_w[2 * warp + 0] = act[i0];
        g_tok_e[2 * warp + 1] = i1; g_tok_w[2 * warp + 1] = act[i1];
        atomicAdd(&g_counts[i0], 1);
        atomicAdd(&g_counts[i1], 1);
    }
}

__global__ void prefix_kernel() {
    if (threadIdx.x == 0 && blockIdx.x == 0) {
        int off = 0;
        for (int e = 0; e < NE; e++) {
            g_offsets[e] = off;
            g_cursor[e]  = off;
            off += ((g_counts[e] + BM - 1) / BM) * BM;
        }
        g_offsets[NE] = off;
    }
}

__global__ void scatter_kernel() {
    int i = blockIdx.x * blockDim.x + threadIdx.x;
    if (i >= NTOK * 2) return;
    int e = g_tok_e[i];
    int slot = atomicAdd(&g_cursor[e], 1);
    g_perm[slot] = i >> 1;
    g_wgt[slot]  = g_tok_w[i];
}

// split fp32 -> (hi, lo) bf16
__global__ void cvt_kernel(const float* __restrict__ src, int n, int sel) {
    int i = (blockIdx.x * blockDim.x + threadIdx.x) * 2;
    if (i >= n) return;
    float2 v = *reinterpret_cast<const float2*>(src + i);
    __nv_bfloat16 h0 = __float2bfloat16(v.x);
    __nv_bfloat16 h1 = __float2bfloat16(v.y);
    __nv_bfloat16 l0 = __float2bfloat16(v.x - __bfloat162float(h0));
    __nv_bfloat16 l1 = __float2bfloat16(v.y - __bfloat162float(h1));
    __nv_bfloat16 *hp, *lp;
    switch (sel) {
        case 0:  hp = g_Xh;  lp = g_Xl;  break;
        case 1:  hp = g_W1h; lp = g_W1l; break;
        case 2:  hp = g_W2h; lp = g_W2l; break;
        case 3:  hp = g_r1h; lp = g_r1l; break;
        default: hp = g_r2h; lp = g_r2l; break;
    }
    *reinterpret_cast<__nv_bfloat162*>(hp + i) = __halves2bfloat162(h0, h1);
    *reinterpret_cast<__nv_bfloat162*>(lp + i) = __halves2bfloat162(l0, l1);
}

__device__ __forceinline__ float silu(float v) { return v / (1.0f + expf(-v)); }

// ---------------- mma.sync helpers ----------------

__device__ __forceinline__ void ldsm4(uint32_t (&r)[4], uint32_t addr) {
    asm volatile("ldmatrix.sync.aligned.m8n8.x4.shared.b16 {%0,%1,%2,%3}, [%4];\n"
        : "=r"(r[0]), "=r"(r[1]), "=r"(r[2]), "=r"(r[3]) : "r"(addr));
}
__device__ __forceinline__ void ldsm4t(uint32_t (&r)[4], uint32_t addr) {
    asm volatile("ldmatrix.sync.aligned.m8n8.x4.trans.shared.b16 {%0,%1,%2,%3}, [%4];\n"
        : "=r"(r[0]), "=r"(r[1]), "=r"(r[2]), "=r"(r[3]) : "r"(addr));
}
__device__ __forceinline__ void mma_bf16(float (&c)[4], const uint32_t (&a)[4],
                                         uint32_t b0, uint32_t b1) {
    asm volatile(
        "mma.sync.aligned.m16n8k16.row.col.f32.bf16.bf16.f32 "
        "{%0,%1,%2,%3}, {%4,%5,%6,%7}, {%8,%9}, {%0,%1,%2,%3};\n"
        : "+f"(c[0]), "+f"(c[1]), "+f"(c[2]), "+f"(c[3])
        : "r"(a[0]), "r"(a[1]), "r"(a[2]), "r"(a[3]), "r"(b0), "r"(b1));
}
__device__ __forceinline__ void cp16(uint32_t dst, const void* src) {
    asm volatile("cp.async.cg.shared.global [%0], [%1], 16;"
                 :: "r"(dst), "l"(src) : "memory");
}
__device__ __forceinline__ void cp_commit() {
    asm volatile("cp.async.commit_group;" ::: "memory");
}
__device__ __forceinline__ void cp_wait2() {
    asm volatile("cp.async.wait_group 2;" ::: "memory");
}
__device__ __forceinline__ uint32_t smem_u32(const void* p) {
    uint32_t a;
    asm("{ .reg .u64 t; cvta.to.shared.u64 t, %1; cvt.u32.u64 %0, t; }"
        : "=r"(a) : "l"(p));
    return a;
}

// MODE 0: Hs = silu(X@W1+b)      MODE 1: Hr = silu(X[perm]@rW1[e]+b)
// MODE 2: out = Hs@W2+b (store)  MODE 3: out[tok] += w*(Hr@rW2[e]+b) (atomic)
template <int MODE, int KDIM, int NDIM>
__device__ __forceinline__ void gemm_body(const float* __restrict__ bias,
                                          float* __restrict__ out) {
    extern __shared__ __align__(16) char sm[];
    const uint32_t smb = smem_u32(sm);
    int*   s_row = reinterpret_cast<int*>(sm + OFF_ROW);
    int*   s_tok = reinterpret_cast<int*>(sm + OFF_TOK);
    float* s_w   = reinterpret_cast<float*>(sm + OFF_W);

    const int tid = threadIdx.x;
    const int rowTile = blockIdx.y * BM;
    const int colTile = blockIdx.x * BN;

    const __nv_bfloat16 *Wh, *Wl;
    const float* bb = bias;
    if constexpr (MODE == 0)      { Wh = g_W1h; Wl = g_W1l; }
    else if constexpr (MODE == 2) { Wh = g_W2h; Wl = g_W2l; }
    else {
        int e = 0;
#pragma unroll
        for (int i = 1; i < NE; i++) if (rowTile >= g_offsets[i]) e = i;
        size_t off = (size_t)e * KDIM * NDIM;
        if constexpr (MODE == 1) { Wh = g_r1h + off; Wl = g_r1l + off; }
        else                     { Wh = g_r2h + off; Wl = g_r2l + off; }
        bb = bias + e * NDIM;
    }
    const __nv_bfloat16 *Agh, *Agl;
    if constexpr (MODE <= 1)      { Agh = g_Xh;  Agl = g_Xl; }
    else if constexpr (MODE == 2) { Agh = g_Hsh; Agl = g_Hsl; }
    else                          { Agh = g_Hrh; Agl = g_Hrl; }

    if (tid < BM) {
        int r = rowTile + tid;
        if constexpr (MODE == 1) s_row[tid] = g_perm[r];
        else                     s_row[tid] = r;
        if constexpr (MODE == 3) { s_tok[tid] = g_perm[r]; s_w[tid] = g_wgt[r]; }
    }
    __syncthreads();

    const int lane = tid & 31, warp = tid >> 5;
    const int wm = warp >> 2;         // 0..1
    const int wn = warp & 3;          // 0..3

    // fill mapping: A 128 rows x 16 cols (2x16B/row), B 16 rows x 128 cols
    const int aR = tid >> 1,  aC = (tid & 1) * 8;
    const int bR = tid >> 4,  bC = (tid & 15) * 8;
    const size_t arow = (size_t)s_row[aR];
    const __nv_bfloat16* Aph = Agh + arow * KDIM + aC;
    const __nv_bfloat16* Apl = Agl + arow * KDIM + aC;
    const __nv_bfloat16* Bph = Wh + (size_t)bR * NDIM + colTile + bC;
    const __nv_bfloat16* Bpl = Wl + (size_t)bR * NDIM + colTile + bC;
    const uint32_t aDstH = smb + OFF_A + aR * 48 + aC * 2;
    const uint32_t bDstH = smb + OFF_B + bR * 272 + bC * 2;

    // ldmatrix lane addresses (stage 0 base)
    const uint32_t sAaddr = smb + OFF_A + (wm * 64 + (lane & 15)) * 48
                          + (lane >> 4) * 16;
    const uint32_t sBaddr = smb + OFF_B + ((lane & 7) + ((lane >> 3) & 1) * 8) * 272
                          + (wn * 32 + (lane >> 4) * 8) * 2;

    float acc[4][4][4] = {};
    constexpr int NK = KDIM / 16;

    // prologue: stages 0..2
#pragma unroll
    for (int s = 0; s < 3; s++) {
        const int kt = s * 16;
        cp16(aDstH + s * A_ST,        Aph + kt);
        cp16(aDstH + s * A_ST + A_HL, Apl + kt);
        cp16(bDstH + s * B_ST,        Bph + (size_t)kt * NDIM);
        cp16(bDstH + s * B_ST + B_HL, Bpl + (size_t)kt * NDIM);
        cp_commit();
    }

    for (int i = 0; i < NK; i++) {
        cp_wait2();
        __syncthreads();
        if (i + 3 < NK) {
            const int s = (i + 3) & 3;
            const int kt = (i + 3) * 16;
            cp16(aDstH + s * A_ST,        Aph + kt);
            cp16(aDstH + s * A_ST + A_HL, Apl + kt);
            cp16(bDstH + s * B_ST,        Bph + (size_t)kt * NDIM);
            cp16(bDstH + s * B_ST + B_HL, Bpl + (size_t)kt * NDIM);
        }
        cp_commit();   // commit every iteration (possibly empty) to keep group count uniform

        const int st = i & 3;
        uint32_t aH[4][4], aL[4][4], bH[2][4], bL[2][4];
#pragma unroll
        for (int mi = 0; mi < 4; mi++) {
            ldsm4(aH[mi], sAaddr + st * A_ST + mi * 768);
            ldsm4(aL[mi], sAaddr + st * A_ST + A_HL + mi * 768);
        }
#pragma unroll
        for (int p = 0; p < 2; p++) {
            ldsm4t(bH[p], sBaddr + st * B_ST + p * 32);
            ldsm4t(bL[p], sBaddr + st * B_ST + B_HL + p * 32);
        }
#pragma unroll
        for (int mi = 0; mi < 4; mi++)
#pragma unroll
            for (int ni = 0; ni < 4; ni++) {
                const int p = ni >> 1, q = (ni & 1) * 2;
                mma_bf16(acc[mi][ni], aH[mi], bH[p][q], bH[p][q + 1]);
                mma_bf16(acc[mi][ni], aH[mi], bL[p][q], bL[p][q + 1]);
                mma_bf16(acc[mi][ni], aL[mi], bH[p][q], bH[p][q + 1]);
            }
        __syncthreads();
    }

    // epilogue
    const int r0 = lane >> 2, c0 = (lane & 3) * 2;
#pragma unroll
    for (int mi = 0; mi < 4; mi++) {
#pragma unroll
        for (int rr = 0; rr < 2; rr++) {
            const int m = wm * 64 + mi * 16 + r0 + rr * 8;
            const int grow = rowTile + m;
#pragma unroll
            for (int ni = 0; ni < 4; ni++) {
                const int col = colTile + wn * 32 + ni * 8 + c0;
                float v0 = acc[mi][ni][rr * 2 + 0] + bb[col];
                float v1 = acc[mi][ni][rr * 2 + 1] + bb[col + 1];
                if constexpr (MODE <= 1) {
                    v0 = silu(v0); v1 = silu(v1);
                    __nv_bfloat16 h0 = __float2bfloat16(v0);
                    __nv_bfloat16 h1 = __float2bfloat16(v1);
                    __nv_bfloat16 l0 = __float2bfloat16(v0 - __bfloat162float(h0));
                    __nv_bfloat16 l1 = __float2bfloat16(v1 - __bfloat162float(h1));
                    __nv_bfloat16* Hh = (MODE == 0 ? g_Hsh : g_Hrh);
                    __nv_bfloat16* Hl = (MODE == 0 ? g_Hsl : g_Hrl);
                    *reinterpret_cast<__nv_bfloat162*>(Hh + (size_t)grow * NDIM + col)
                        = __halves2bfloat162(h0, h1);
                    *reinterpret_cast<__nv_bfloat162*>(Hl + (size_t)grow * NDIM + col)
                        = __halves2bfloat162(l0, l1);
                } else if constexpr (MODE == 2) {
                    *reinterpret_cast<float2*>(out + (size_t)grow * NDIM + col)
                        = make_float2(v0, v1);
                } else {
                    const float w = s_w[m];
                    float* dst = out + (size_t)s_tok[m] * NDIM + col;
                    atomicAdd(dst + 0, w * v0);
                    atomicAdd(dst + 1, w * v1);
                }
            }
        }
    }
}

__global__ void __launch_bounds__(256) gemm_m0(const float* __restrict__ bias) {
    gemm_body<0, D, HD>(bias, nullptr);
}
__global__ void __launch_bounds__(256) gemm_m1(const float* __restrict__ bias) {
    gemm_body<1, D, HD>(bias, nullptr);
}
__global__ void __launch_bounds__(256) gemm_m2(const float* __restrict__ bias,
                                               float* __restrict__ out) {
    gemm_body<2, HD, D>(bias, out);
}
__global__ void __launch_bounds__(256) gemm_m3(const float* __restrict__ bias,
                                               float* __restrict__ out) {
    gemm_body<3, HD, D>(bias, out);
}

extern "C" void kernel_launch(void* const* d_in, const int* in_sizes, int n_in,
                              void* d_out, int out_size) {
    (void)in_sizes; (void)n_in; (void)out_size;
    const float* X   = (const float*)d_in[0];
    const float* RW  = (const float*)d_in[1];
    const float* EB  = (const float*)d_in[2];
    const float* sW1 = (const float*)d_in[3];
    const float* sb1 = (const float*)d_in[4];
    const float* sW2 = (const float*)d_in[5];
    const float* sb2 = (const float*)d_in[6];
    const float* rW1 = (const float*)d_in[7];
    const float* rb1 = (const float*)d_in[8];
    const float* rW2 = (const float*)d_in[9];
    const float* rb2 = (const float*)d_in[10];
    float* out = (float*)d_out;

    cudaFuncSetAttribute(gemm_m0, cudaFuncAttributeMaxDynamicSharedMemorySize, SMEM_BYTES);
    cudaFuncSetAttribute(gemm_m1, cudaFuncAttributeMaxDynamicSharedMemorySize, SMEM_BYTES);
    cudaFuncSetAttribute(gemm_m2, cudaFuncAttributeMaxDynamicSharedMemorySize, SMEM_BYTES);
    cudaFuncSetAttribute(gemm_m3, cudaFuncAttributeMaxDynamicSharedMemorySize, SMEM_BYTES);

    init_kernel<<<(CAP + 255) / 256, 256>>>();
    routing_kernel<<<NTOK / 8, 256>>>(X, RW, EB);
    prefix_kernel<<<1, 32>>>();
    scatter_kernel<<<(NTOK * 2) / 256, 256>>>();

    cvt_kernel<<<(NTOK * D / 2 + 255) / 256, 256>>>(X, NTOK * D, 0);
    cvt_kernel<<<(D * HD / 2 + 255) / 256, 256>>>(sW1, D * HD, 1);
    cvt_kernel<<<(HD * D / 2 + 255) / 256, 256>>>(sW2, HD * D, 2);
    cvt_kernel<<<(NE * D * HD / 2 + 255) / 256, 256>>>(rW1, NE * D * HD, 3);
    cvt_kernel<<<(NE * HD * D / 2 + 255) / 256, 256>>>(rW2, NE * HD * D, 4);

    gemm_m0<<<dim3(HD / BN, NTOK / BM), 256, SMEM_BYTES>>>(sb1);
    gemm_m1<<<dim3(HD / BN, CAP / BM), 256, SMEM_BYTES>>>(rb1);
    gemm_m2<<<dim3(D / BN, NTOK / BM), 256, SMEM_BYTES>>>(sb2, out);
    gemm_m3<<<dim3(D / BN, CAP / BM), 256, SMEM_BYTES>>>(rb2, out);
}

// round 7
// speedup vs baseline: 1.0100x; 1.0100x over previous
#include <cuda_runtime.h>
#include <cuda_bf16.h>
#include <cstdint>
#include <math.h>

namespace {
constexpr int NTOK = 8192;
constexpr int D    = 1024;
constexpr int HD   = 512;
constexpr int NE   = 8;
constexpr int BM = 128, BN = 128;
constexpr int CAP  = 17408;            // 2*NTOK + per-expert pad to 128

// dynamic smem layout (bytes)
constexpr int OFF_ROW = 0;             // int[128]
constexpr int OFF_TOK = 512;           // int[128]
constexpr int OFF_W   = 1024;          // float[128]
constexpr int OFF_A   = 1536;
constexpr int A_HL    = 128 * 24 * 2;  // 6144  (one hi or lo buffer)
constexpr int A_ST    = 2 * A_HL;      // 12288 (per stage: hi+lo)
constexpr int OFF_B   = OFF_A + 4 * A_ST;   // 50688
constexpr int B_HL    = 16 * 136 * 2;  // 4352
constexpr int B_ST    = 2 * B_HL;      // 8704
constexpr int SMEM_BYTES = OFF_B + 4 * B_ST;  // 85504
}

__device__ int   g_counts[NE];
__device__ int   g_offsets[NE + 1];
__device__ int   g_cursor[NE];
__device__ int   g_perm[CAP];
__device__ float g_wgt[CAP];
__device__ int   g_tok_e[NTOK * 2];
__device__ float g_tok_w[NTOK * 2];

// split-bf16 operands, row-major (weights [K,N])
__device__ __align__(16) __nv_bfloat16 g_Xh[NTOK * D],  g_Xl[NTOK * D];
__device__ __align__(16) __nv_bfloat16 g_W1h[D * HD],  g_W1l[D * HD];
__device__ __align__(16) __nv_bfloat16 g_W2h[HD * D],  g_W2l[HD * D];
__device__ __align__(16) __nv_bfloat16 g_r1h[NE * D * HD], g_r1l[NE * D * HD];
__device__ __align__(16) __nv_bfloat16 g_r2h[NE * HD * D], g_r2l[NE * HD * D];
__device__ __align__(16) __nv_bfloat16 g_Hsh[NTOK * HD], g_Hsl[NTOK * HD];
__device__ __align__(16) __nv_bfloat16 g_Hrh[(size_t)CAP * HD], g_Hrl[(size_t)CAP * HD];

// ---------------- routing / bookkeeping ----------------

__global__ void init_kernel() {
    int i = blockIdx.x * blockDim.x + threadIdx.x;
    if (i < NE) g_counts[i] = 0;
    if (i < CAP) { g_perm[i] = 0; g_wgt[i] = 0.0f; }
}

__global__ void routing_kernel(const float* __restrict__ X,
                               const float* __restrict__ RW,
                               const float* __restrict__ EB) {
    int warp = (blockIdx.x * blockDim.x + threadIdx.x) >> 5;
    int lane = threadIdx.x & 31;
    if (warp >= NTOK) return;
    const float* x = X + (size_t)warp * D;
    float acc[NE];
#pragma unroll
    for (int e = 0; e < NE; e++) acc[e] = 0.0f;
    for (int k = lane; k < D; k += 32) {
        float xv = x[k];
#pragma unroll
        for (int e = 0; e < NE; e++) acc[e] = fmaf(xv, RW[e * D + k], acc[e]);
    }
#pragma unroll
    for (int e = 0; e < NE; e++) {
#pragma unroll
        for (int o = 16; o > 0; o >>= 1)
            acc[e] += __shfl_down_sync(0xffffffffu, acc[e], o);
    }
    if (lane == 0) {
        float act[NE];
#pragma unroll
        for (int e = 0; e < NE; e++) {
            float l = acc[e] + EB[e];
            float sp = (l > 0.0f) ? (l + log1pf(expf(-l))) : log1pf(expf(l));
            act[e] = sqrtf(sp);
        }
        int i0 = 0;
#pragma unroll
        for (int e = 1; e < NE; e++) if (act[e] > act[i0]) i0 = e;
        int i1 = (i0 == 0) ? 1 : 0;
#pragma unroll
        for (int e = 0; e < NE; e++)
            if (e != i0 && act[e] > act[i1]) i1 = e;
        g_tok_e[2 * warp + 0] = i0; g_tok_w[2 * warp + 0] = act[i0];
        g_tok_e[2 * warp + 1] = i1; g_tok_w[2 * warp + 1] = act[i1];
        atomicAdd(&g_counts[i0], 1);
        atomicAdd(&g_counts[i1], 1);
    }
}

__global__ void prefix_kernel() {
    if (threadIdx.x == 0 && blockIdx.x == 0) {
        int off = 0;
        for (int e = 0; e < NE; e++) {
            g_offsets[e] = off;
            g_cursor[e]  = off;
            off += ((g_counts[e] + BM - 1) / BM) * BM;
        }
        g_offsets[NE] = off;
    }
}

__global__ void scatter_kernel() {
    int i = blockIdx.x * blockDim.x + threadIdx.x;
    if (i >= NTOK * 2) return;
    int e = g_tok_e[i];
    int slot = atomicAdd(&g_cursor[e], 1);
    g_perm[slot] = i >> 1;
    g_wgt[slot]  = g_tok_w[i];
}

// split fp32 -> (hi, lo) bf16
__global__ void cvt_kernel(const float* __restrict__ src, int n, int sel) {
    int i = (blockIdx.x * blockDim.x + threadIdx.x) * 2;
    if (i >= n) return;
    float2 v = *reinterpret_cast<const float2*>(src + i);
    __nv_bfloat16 h0 = __float2bfloat16(v.x);
    __nv_bfloat16 h1 = __float2bfloat16(v.y);
    __nv_bfloat16 l0 = __float2bfloat16(v.x - __bfloat162float(h0));
    __nv_bfloat16 l1 = __float2bfloat16(v.y - __bfloat162float(h1));
    __nv_bfloat16 *hp, *lp;
    switch (sel) {
        case 0:  hp = g_Xh;  lp = g_Xl;  break;
        case 1:  hp = g_W1h; lp = g_W1l; break;
        case 2:  hp = g_W2h; lp = g_W2l; break;
        case 3:  hp = g_r1h; lp = g_r1l; break;
        default: hp = g_r2h; lp = g_r2l; break;
    }
    *reinterpret_cast<__nv_bfloat162*>(hp + i) = __halves2bfloat162(h0, h1);
    *reinterpret_cast<__nv_bfloat162*>(lp + i) = __halves2bfloat162(l0, l1);
}

__device__ __forceinline__ float silu(float v) { return v / (1.0f + expf(-v)); }

// ---------------- mma.sync helpers ----------------

__device__ __forceinline__ void ldsm4(uint32_t (&r)[4], uint32_t addr) {
    asm volatile("ldmatrix.sync.aligned.m8n8.x4.shared.b16 {%0,%1,%2,%3}, [%4];\n"
        : "=r"(r[0]), "=r"(r[1]), "=r"(r[2]), "=r"(r[3]) : "r"(addr));
}
__device__ __forceinline__ void ldsm4t(uint32_t (&r)[4], uint32_t addr) {
    asm volatile("ldmatrix.sync.aligned.m8n8.x4.trans.shared.b16 {%0,%1,%2,%3}, [%4];\n"
        : "=r"(r[0]), "=r"(r[1]), "=r"(r[2]), "=r"(r[3]) : "r"(addr));
}
__device__ __forceinline__ void mma_bf16(float (&c)[4], const uint32_t (&a)[4],
                                         uint32_t b0, uint32_t b1) {
    asm volatile(
        "mma.sync.aligned.m16n8k16.row.col.f32.bf16.bf16.f32 "
        "{%0,%1,%2,%3}, {%4,%5,%6,%7}, {%8,%9}, {%0,%1,%2,%3};\n"
        : "+f"(c[0]), "+f"(c[1]), "+f"(c[2]), "+f"(c[3])
        : "r"(a[0]), "r"(a[1]), "r"(a[2]), "r"(a[3]), "r"(b0), "r"(b1));
}
__device__ __forceinline__ void cp16(uint32_t dst, const void* src) {
    asm volatile("cp.async.cg.shared.global [%0], [%1], 16;"
                 :: "r"(dst), "l"(src) : "memory");
}
__device__ __forceinline__ void cp_commit() {
    asm volatile("cp.async.commit_group;" ::: "memory");
}
__device__ __forceinline__ void cp_wait2() {
    asm volatile("cp.async.wait_group 2;" ::: "memory");
}
__device__ __forceinline__ uint32_t smem_u32(const void* p) {
    uint32_t a;
    asm("{ .reg .u64 t; cvta.to.shared.u64 t, %1; cvt.u32.u64 %0, t; }"
        : "=r"(a) : "l"(p));
    return a;
}

// MODE 0: Hs = silu(X@W1+b)      MODE 1: Hr = silu(X[perm]@rW1[e]+b)
// MODE 2: out = Hs@W2+b (store)  MODE 3: out[tok] += w*(Hr@rW2[e]+b) (atomic)
template <int MODE, int KDIM, int NDIM>
__device__ __forceinline__ void gemm_body(const float* __restrict__ bias,
                                          float* __restrict__ out) {
    extern __shared__ __align__(16) char sm[];
    const uint32_t smb = smem_u32(sm);
    int*   s_row = reinterpret_cast<int*>(sm + OFF_ROW);
    int*   s_tok = reinterpret_cast<int*>(sm + OFF_TOK);
    float* s_w   = reinterpret_cast<float*>(sm + OFF_W);

    const int tid = threadIdx.x;
    const int rowTile = blockIdx.y * BM;
    const int colTile = blockIdx.x * BN;

    const __nv_bfloat16 *Wh, *Wl;
    const float* bb = bias;
    if constexpr (MODE == 0)      { Wh = g_W1h; Wl = g_W1l; }
    else if constexpr (MODE == 2) { Wh = g_W2h; Wl = g_W2l; }
    else {
        int e = 0;
#pragma unroll
        for (int i = 1; i < NE; i++) if (rowTile >= g_offsets[i]) e = i;
        size_t off = (size_t)e * KDIM * NDIM;
        if constexpr (MODE == 1) { Wh = g_r1h + off; Wl = g_r1l + off; }
        else                     { Wh = g_r2h + off; Wl = g_r2l + off; }
        bb = bias + e * NDIM;
    }
    const __nv_bfloat16 *Agh, *Agl;
    if constexpr (MODE <= 1)      { Agh = g_Xh;  Agl = g_Xl; }
    else if constexpr (MODE == 2) { Agh = g_Hsh; Agl = g_Hsl; }
    else                          { Agh = g_Hrh; Agl = g_Hrl; }

    if (tid < BM) {
        int r = rowTile + tid;
        if constexpr (MODE == 1) s_row[tid] = g_perm[r];
        else                     s_row[tid] = r;
        if constexpr (MODE == 3) { s_tok[tid] = g_perm[r]; s_w[tid] = g_wgt[r]; }
    }
    __syncthreads();

    const int lane = tid & 31, warp = tid >> 5;
    const int wm = warp >> 2;         // 0..1
    const int wn = warp & 3;          // 0..3

    // fill mapping: A 128 rows x 16 cols (2x16B/row), B 16 rows x 128 cols
    const int aR = tid >> 1,  aC = (tid & 1) * 8;
    const int bR = tid >> 4,  bC = (tid & 15) * 8;
    const size_t arow = (size_t)s_row[aR];
    const __nv_bfloat16* Aph = Agh + arow * KDIM + aC;
    const __nv_bfloat16* Apl = Agl + arow * KDIM + aC;
    const __nv_bfloat16* Bph = Wh + (size_t)bR * NDIM + colTile + bC;
    const __nv_bfloat16* Bpl = Wl + (size_t)bR * NDIM + colTile + bC;
    const uint32_t aDstH = smb + OFF_A + aR * 48 + aC * 2;
    const uint32_t bDstH = smb + OFF_B + bR * 272 + bC * 2;

    // ldmatrix lane addresses (stage 0 base)
    const uint32_t sAaddr = smb + OFF_A + (wm * 64 + (lane & 15)) * 48
                          + (lane >> 4) * 16;
    const uint32_t sBaddr = smb + OFF_B + ((lane & 7) + ((lane >> 3) & 1) * 8) * 272
                          + (wn * 32 + (lane >> 4) * 8) * 2;

    float acc[4][4][4] = {};
    constexpr int NK = KDIM / 16;

    // prologue: stages 0..2
#pragma unroll
    for (int s = 0; s < 3; s++) {
        const int kt = s * 16;
        cp16(aDstH + s * A_ST,        Aph + kt);
        cp16(aDstH + s * A_ST + A_HL, Apl + kt);
        cp16(bDstH + s * B_ST,        Bph + (size_t)kt * NDIM);
        cp16(bDstH + s * B_ST + B_HL, Bpl + (size_t)kt * NDIM);
        cp_commit();
    }

    for (int i = 0; i < NK; i++) {
        cp_wait2();
        __syncthreads();
        if (i + 3 < NK) {
            const int s = (i + 3) & 3;
            const int kt = (i + 3) * 16;
            cp16(aDstH + s * A_ST,        Aph + kt);
            cp16(aDstH + s * A_ST + A_HL, Apl + kt);
            cp16(bDstH + s * B_ST,        Bph + (size_t)kt * NDIM);
            cp16(bDstH + s * B_ST + B_HL, Bpl + (size_t)kt * NDIM);
        }
        cp_commit();   // commit every iteration (possibly empty) to keep group count uniform

        const int st = i & 3;
        uint32_t aH[4][4], aL[4][4], bH[2][4], bL[2][4];
#pragma unroll
        for (int mi = 0; mi < 4; mi++) {
            ldsm4(aH[mi], sAaddr + st * A_ST + mi * 768);
            ldsm4(aL[mi], sAaddr + st * A_ST + A_HL + mi * 768);
        }
#pragma unroll
        for (int p = 0; p < 2; p++) {
            ldsm4t(bH[p], sBaddr + st * B_ST + p * 32);
            ldsm4t(bL[p], sBaddr + st * B_ST + B_HL + p * 32);
        }
#pragma unroll
        for (int mi = 0; mi < 4; mi++)
#pragma unroll
            for (int ni = 0; ni < 4; ni++) {
                const int p = ni >> 1, q = (ni & 1) * 2;
                mma_bf16(acc[mi][ni], aH[mi], bH[p][q], bH[p][q + 1]);
                mma_bf16(acc[mi][ni], aH[mi], bL[p][q], bL[p][q + 1]);
                mma_bf16(acc[mi][ni], aL[mi], bH[p][q], bH[p][q + 1]);
            }
        __syncthreads();
    }

    // epilogue
    const int r0 = lane >> 2, c0 = (lane & 3) * 2;
#pragma unroll
    for (int mi = 0; mi < 4; mi++) {
#pragma unroll
        for (int rr = 0; rr < 2; rr++) {
            const int m = wm * 64 + mi * 16 + r0 + rr * 8;
            const int grow = rowTile + m;
#pragma unroll
            for (int ni = 0; ni < 4; ni++) {
                const int col = colTile + wn * 32 + ni * 8 + c0;
                float v0 = acc[mi][ni][rr * 2 + 0] + bb[col];
                float v1 = acc[mi][ni][rr * 2 + 1] + bb[col + 1];
                if constexpr (MODE <= 1) {
                    v0 = silu(v0); v1 = silu(v1);
                    __nv_bfloat16 h0 = __float2bfloat16(v0);
                    __nv_bfloat16 h1 = __float2bfloat16(v1);
                    __nv_bfloat16 l0 = __float2bfloat16(v0 - __bfloat162float(h0));
                    __nv_bfloat16 l1 = __float2bfloat16(v1 - __bfloat162float(h1));
                    __nv_bfloat16* Hh = (MODE == 0 ? g_Hsh : g_Hrh);
                    __nv_bfloat16* Hl = (MODE == 0 ? g_Hsl : g_Hrl);
                    *reinterpret_cast<__nv_bfloat162*>(Hh + (size_t)grow * NDIM + col)
                        = __halves2bfloat162(h0, h1);
                    *reinterpret_cast<__nv_bfloat162*>(Hl + (size_t)grow * NDIM + col)
                        = __halves2bfloat162(l0, l1);
                } else if constexpr (MODE == 2) {
                    *reinterpret_cast<float2*>(out + (size_t)grow * NDIM + col)
                        = make_float2(v0, v1);
                } else {
                    const float w = s_w[m];
                    float* dst = out + (size_t)s_tok[m] * NDIM + col;
                    atomicAdd(dst + 0, w * v0);
                    atomicAdd(dst + 1, w * v1);
                }
            }
        }
    }
}

__global__ void __launch_bounds__(256) gemm_m0(const float* __restrict__ bias) {
    gemm_body<0, D, HD>(bias, nullptr);
}
__global__ void __launch_bounds__(256) gemm_m1(const float* __restrict__ bias) {
    gemm_body<1, D, HD>(bias, nullptr);
}
__global__ void __launch_bounds__(256) gemm_m2(const float* __restrict__ bias,
                                               float* __restrict__ out) {
    gemm_body<2, HD, D>(bias, out);
}
__global__ void __launch_bounds__(256) gemm_m3(const float* __restrict__ bias,
                                               float* __restrict__ out) {
    gemm_body<3, HD, D>(bias, out);
}

extern "C" void kernel_launch(void* const* d_in, const int* in_sizes, int n_in,
                              void* d_out, int out_size) {
    (void)in_sizes; (void)n_in; (void)out_size;
    const float* X   = (const float*)d_in[0];
    const float* RW  = (const float*)d_in[1];
    const float* EB  = (const float*)d_in[2];
    const float* sW1 = (const float*)d_in[3];
    const float* sb1 = (const float*)d_in[4];
    const float* sW2 = (const float*)d_in[5];
    const float* sb2 = (const float*)d_in[6];
    const float* rW1 = (const float*)d_in[7];
    const float* rb1 = (const float*)d_in[8];
    const float* rW2 = (const float*)d_in[9];
    const float* rb2 = (const float*)d_in[10];
    float* out = (float*)d_out;

    cudaFuncSetAttribute(gemm_m0, cudaFuncAttributeMaxDynamicSharedMemorySize, SMEM_BYTES);
    cudaFuncSetAttribute(gemm_m1, cudaFuncAttributeMaxDynamicSharedMemorySize, SMEM_BYTES);
    cudaFuncSetAttribute(gemm_m2, cudaFuncAttributeMaxDynamicSharedMemorySize, SMEM_BYTES);
    cudaFuncSetAttribute(gemm_m3, cudaFuncAttributeMaxDynamicSharedMemorySize, SMEM_BYTES);

    init_kernel<<<(CAP + 255) / 256, 256>>>();
    routing_kernel<<<NTOK / 8, 256>>>(X, RW, EB);
    prefix_kernel<<<1, 32>>>();
    scatter_kernel<<<(NTOK * 2) / 256, 256>>>();

    cvt_kernel<<<(NTOK * D / 2 + 255) / 256, 256>>>(X, NTOK * D, 0);
    cvt_kernel<<<(D * HD / 2 + 255) / 256, 256>>>(sW1, D * HD, 1);
    cvt_kernel<<<(HD * D / 2 + 255) / 256, 256>>>(sW2, HD * D, 2);
    cvt_kernel<<<(NE * D * HD / 2 + 255) / 256, 256>>>(rW1, NE * D * HD, 3);
    cvt_kernel<<<(NE * HD * D / 2 + 255) / 256, 256>>>(rW2, NE * HD * D, 4);

    gemm_m0<<<dim3(HD / BN, NTOK / BM), 256, SMEM_BYTES>>>(sb1);
    gemm_m1<<<dim3(HD / BN, CAP / BM), 256, SMEM_BYTES>>>(rb1);
    gemm_m2<<<dim3(D / BN, NTOK / BM), 256, SMEM_BYTES>>>(sb2, out);
    gemm_m3<<<dim3(D / BN, CAP / BM), 256, SMEM_BYTES>>>(rb2, out);
}

// round 10
// speedup vs baseline: 1.1077x; 1.0967x over previous
#include <cuda_runtime.h>
#include <cuda_fp16.h>
#include <cstdint>
#include <math.h>

namespace {
constexpr int NTOK = 8192;
constexpr int D    = 1024;
constexpr int HD   = 512;
constexpr int NE   = 8;
constexpr int BM = 128, BN = 128;
constexpr int CAP  = 17408;            // 2*NTOK + per-expert pad to 128
constexpr float LO_SCALE  = 2048.0f;
constexpr float INV_LO    = 1.0f / 2048.0f;
}

__device__ int   g_counts[NE];
__device__ int   g_offsets[NE + 1];
__device__ int   g_cursor[NE];
__device__ int   g_perm[CAP];
__device__ float g_wgt[CAP];
__device__ int   g_tok_e[NTOK * 2];
__device__ float g_tok_w[NTOK * 2];

// fp16 operands. A single-plane; weights two planes (lo pre-scaled x2048), [K,N].
__device__ __align__(16) __half g_Xh[NTOK * D];
__device__ __align__(16) __half g_W1h[D * HD],  g_W1l[D * HD];
__device__ __align__(16) __half g_W2h[HD * D],  g_W2l[HD * D];
__device__ __align__(16) __half g_r1h[NE * D * HD], g_r1l[NE * D * HD];
__device__ __align__(16) __half g_r2h[NE * HD * D], g_r2l[NE * HD * D];
__device__ __align__(16) __half g_Hsh[NTOK * HD];
__device__ __align__(16) __half g_Hrh[(size_t)CAP * HD];

// ---------------- routing / bookkeeping ----------------

__global__ void init_kernel() {
    int i = blockIdx.x * blockDim.x + threadIdx.x;
    if (i < NE) g_counts[i] = 0;
    if (i < CAP) { g_perm[i] = 0; g_wgt[i] = 0.0f; }
}

__global__ void routing_kernel(const float* __restrict__ X,
                               const float* __restrict__ RW,
                               const float* __restrict__ EB) {
    int warp = (blockIdx.x * blockDim.x + threadIdx.x) >> 5;
    int lane = threadIdx.x & 31;
    if (warp >= NTOK) return;
    const float* x = X + (size_t)warp * D;
    float acc[NE];
#pragma unroll
    for (int e = 0; e < NE; e++) acc[e] = 0.0f;
    for (int k = lane; k < D; k += 32) {
        float xv = x[k];
#pragma unroll
        for (int e = 0; e < NE; e++) acc[e] = fmaf(xv, RW[e * D + k], acc[e]);
    }
#pragma unroll
    for (int e = 0; e < NE; e++) {
#pragma unroll
        for (int o = 16; o > 0; o >>= 1)
            acc[e] += __shfl_down_sync(0xffffffffu, acc[e], o);
    }
    if (lane == 0) {
        float act[NE];
#pragma unroll
        for (int e = 0; e < NE; e++) {
            float l = acc[e] + EB[e];
            float sp = (l > 0.0f) ? (l + log1pf(expf(-l))) : log1pf(expf(l));
            act[e] = sqrtf(sp);
        }
        int i0 = 0;
#pragma unroll
        for (int e = 1; e < NE; e++) if (act[e] > act[i0]) i0 = e;
        int i1 = (i0 == 0) ? 1 : 0;
#pragma unroll
        for (int e = 0; e < NE; e++)
            if (e != i0 && act[e] > act[i1]) i1 = e;
        g_tok_e[2 * warp + 0] = i0; g_tok_w[2 * warp + 0] = act[i0];
        g_tok_e[2 * warp + 1] = i1; g_tok_w[2 * warp + 1] = act[i1];
        atomicAdd(&g_counts[i0], 1);
        atomicAdd(&g_counts[i1], 1);
    }
}

__global__ void prefix_kernel() {
    if (threadIdx.x == 0 && blockIdx.x == 0) {
        int off = 0;
        for (int e = 0; e < NE; e++) {
            g_offsets[e] = off;
            g_cursor[e]  = off;
            off += ((g_counts[e] + BM - 1) / BM) * BM;
        }
        g_offsets[NE] = off;
    }
}

__global__ void scatter_kernel() {
    int i = blockIdx.x * blockDim.x + threadIdx.x;
    if (i >= NTOK * 2) return;
    int e = g_tok_e[i];
    int slot = atomicAdd(&g_cursor[e], 1);
    g_perm[slot] = i >> 1;
    g_wgt[slot]  = g_tok_w[i];
}

// X -> single fp16 plane
__global__ void cvt_x_kernel(const float* __restrict__ src, int n) {
    int i = (blockIdx.x * blockDim.x + threadIdx.x) * 2;
    if (i >= n) return;
    float2 v = *reinterpret_cast<const float2*>(src + i);
    *reinterpret_cast<__half2*>(g_Xh + i) =
        __halves2half2(__float2half(v.x), __float2half(v.y));
}

// weights -> fp16 hi plane + (residual*2048) lo plane, same [K,N] layout
__global__ void cvt_w_kernel(const float* __restrict__ src, int n, int sel) {
    int i = (blockIdx.x * blockDim.x + threadIdx.x) * 2;
    if (i >= n) return;
    float2 v = *reinterpret_cast<const float2*>(src + i);
    __half h0 = __float2half(v.x);
    __half h1 = __float2half(v.y);
    __half l0 = __float2half((v.x - __half2float(h0)) * LO_SCALE);
    __half l1 = __float2half((v.y - __half2float(h1)) * LO_SCALE);
    __half *hp, *lp;
    switch (sel) {
        case 1:  hp = g_W1h; lp = g_W1l; break;
        case 2:  hp = g_W2h; lp = g_W2l; break;
        case 3:  hp = g_r1h; lp = g_r1l; break;
        default: hp = g_r2h; lp = g_r2l; break;
    }
    *reinterpret_cast<__half2*>(hp + i) = __halves2half2(h0, h1);
    *reinterpret_cast<__half2*>(lp + i) = __halves2half2(l0, l1);
}

__device__ __forceinline__ float silu(float v) { return v / (1.0f + expf(-v)); }

// ---------------- mma helpers ----------------

__device__ __forceinline__ void ldsm4(uint32_t (&r)[4], uint32_t addr) {
    asm volatile("ldmatrix.sync.aligned.m8n8.x4.shared.b16 {%0,%1,%2,%3}, [%4];\n"
        : "=r"(r[0]), "=r"(r[1]), "=r"(r[2]), "=r"(r[3]) : "r"(addr));
}
__device__ __forceinline__ void ldsm4t(uint32_t (&r)[4], uint32_t addr) {
    asm volatile("ldmatrix.sync.aligned.m8n8.x4.trans.shared.b16 {%0,%1,%2,%3}, [%4];\n"
        : "=r"(r[0]), "=r"(r[1]), "=r"(r[2]), "=r"(r[3]) : "r"(addr));
}
__device__ __forceinline__ void mma_f16(float (&c)[4], const uint32_t (&a)[4],
                                        uint32_t b0, uint32_t b1) {
    asm volatile(
        "mma.sync.aligned.m16n8k16.row.col.f32.f16.f16.f32 "
        "{%0,%1,%2,%3}, {%4,%5,%6,%7}, {%8,%9}, {%0,%1,%2,%3};\n"
        : "+f"(c[0]), "+f"(c[1]), "+f"(c[2]), "+f"(c[3])
        : "r"(a[0]), "r"(a[1]), "r"(a[2]), "r"(a[3]), "r"(b0), "r"(b1));
}

// MODE 0: Hs = silu(X@W1+b)      MODE 1: Hr = silu(X[perm]@rW1[e]+b)
// MODE 2: out = Hs@W2+b (store)  MODE 3: out[tok] += w*(Hr@rW2[e]+b) (atomic)
template <int MODE, int KDIM, int NDIM>
__device__ __forceinline__ void gemm_body(const float* __restrict__ bias,
                                          float* __restrict__ out) {
    __shared__ __align__(16) __half sA[2][128][24];      // [stage][m][k]
    __shared__ __align__(16) __half sB[2][2][16][136];   // [stage][hi/lo][k][n]
    __shared__ int   s_row[128];
    __shared__ int   s_tok[128];
    __shared__ float s_w[128];

    const int tid = threadIdx.x;
    const int rowTile = blockIdx.y * BM;
    const int colTile = blockIdx.x * BN;

    const __half *Wh, *Wl;
    const float* bb = bias;
    if constexpr (MODE == 0)      { Wh = g_W1h; Wl = g_W1l; }
    else if constexpr (MODE == 2) { Wh = g_W2h; Wl = g_W2l; }
    else {
        int e = 0;
#pragma unroll
        for (int i = 1; i < NE; i++) if (rowTile >= g_offsets[i]) e = i;
        size_t off = (size_t)e * KDIM * NDIM;
        if constexpr (MODE == 1) { Wh = g_r1h + off; Wl = g_r1l + off; }
        else                     { Wh = g_r2h + off; Wl = g_r2l + off; }
        bb = bias + e * NDIM;
    }
    const __half* Ag;
    if constexpr (MODE <= 1)      Ag = g_Xh;
    else if constexpr (MODE == 2) Ag = g_Hsh;
    else                          Ag = g_Hrh;

    if (tid < BM) {
        int r = rowTile + tid;
        if constexpr (MODE == 1) s_row[tid] = g_perm[r];
        else                     s_row[tid] = r;
        if constexpr (MODE == 3) { s_tok[tid] = g_perm[r]; s_w[tid] = g_wgt[r]; }
    }
    __syncthreads();

    const int lane = tid & 31, warp = tid >> 5;
    const int wm = warp >> 2;     // 0..1 -> 64 rows each
    const int wn = warp & 3;      // 0..3 -> 32 cols each

    // staging (global->reg->smem)
    const int aR = tid >> 1,  aC = (tid & 1) * 8;
    const int bR = tid >> 4,  bC = (tid & 15) * 8;
    const size_t arow = (size_t)s_row[aR];
    const __half* Ap  = Ag + arow * KDIM + aC;
    const __half* Bph = Wh + (size_t)bR * NDIM + colTile + bC;
    const __half* Bpl = Wl + (size_t)bR * NDIM + colTile + bC;

    // ldmatrix lane addresses
    uint32_t sAaddr = (uint32_t)__cvta_generic_to_shared(
        &sA[0][wm * 64 + (lane & 15)][(lane >> 4) * 8]);
    uint32_t sBaddr = (uint32_t)__cvta_generic_to_shared(
        &sB[0][0][(lane & 7) + ((lane >> 3) & 1) * 8][wn * 32 + (lane >> 4) * 8]);
    constexpr uint32_t A_STAGE = 128 * 24 * 2;     // 6144
    constexpr uint32_t B_HL    = 16 * 136 * 2;     // 4352
    constexpr uint32_t B_STAGE = 2 * B_HL;         // 8704

    float acc0[4][4][4] = {}, acc1[4][4][4] = {};
    uint4 rA, rBh, rBl;

    // prologue: stage 0
    rA  = *reinterpret_cast<const uint4*>(Ap);
    rBh = *reinterpret_cast<const uint4*>(Bph);
    rBl = *reinterpret_cast<const uint4*>(Bpl);
    *reinterpret_cast<uint4*>(&sA[0][aR][aC])    = rA;
    *reinterpret_cast<uint4*>(&sB[0][0][bR][bC]) = rBh;
    *reinterpret_cast<uint4*>(&sB[0][1][bR][bC]) = rBl;
    __syncthreads();

    int st = 0;
    for (int kt = 0; kt < KDIM; kt += 16) {
        const bool more = (kt + 16 < KDIM);
        if (more) {
            rA  = *reinterpret_cast<const uint4*>(Ap + kt + 16);
            rBh = *reinterpret_cast<const uint4*>(Bph + (size_t)(kt + 16) * NDIM);
            rBl = *reinterpret_cast<const uint4*>(Bpl + (size_t)(kt + 16) * NDIM);
        }
        uint32_t aF[4][4], bH[2][4], bL[2][4];
#pragma unroll
        for (int mi = 0; mi < 4; mi++)
            ldsm4(aF[mi], sAaddr + st * A_STAGE + mi * (16 * 24 * 2));
#pragma unroll
        for (int p = 0; p < 2; p++) {
            ldsm4t(bH[p], sBaddr + st * B_STAGE + p * (16 * 2));
            ldsm4t(bL[p], sBaddr + st * B_STAGE + B_HL + p * (16 * 2));
        }
#pragma unroll
        for (int mi = 0; mi < 4; mi++)
#pragma unroll
            for (int ni = 0; ni < 4; ni++) {
                const int p = ni >> 1, q = (ni & 1) * 2;
                mma_f16(acc0[mi][ni], aF[mi], bH[p][q], bH[p][q + 1]);
                mma_f16(acc1[mi][ni], aF[mi], bL[p][q], bL[p][q + 1]);
            }
        if (more) {
            *reinterpret_cast<uint4*>(&sA[st ^ 1][aR][aC])    = rA;
            *reinterpret_cast<uint4*>(&sB[st ^ 1][0][bR][bC]) = rBh;
            *reinterpret_cast<uint4*>(&sB[st ^ 1][1][bR][bC]) = rBl;
        }
        st ^= 1;
        __syncthreads();
    }

    // epilogue
    const int r0 = lane >> 2, c0 = (lane & 3) * 2;
#pragma unroll
    for (int mi = 0; mi < 4; mi++) {
#pragma unroll
        for (int rr = 0; rr < 2; rr++) {
            const int m = wm * 64 + mi * 16 + r0 + rr * 8;
            const int grow = rowTile + m;
#pragma unroll
            for (int ni = 0; ni < 4; ni++) {
                const int col = colTile + wn * 32 + ni * 8 + c0;
                float v0 = acc0[mi][ni][rr * 2 + 0]
                         + acc1[mi][ni][rr * 2 + 0] * INV_LO + bb[col];
                float v1 = acc0[mi][ni][rr * 2 + 1]
                         + acc1[mi][ni][rr * 2 + 1] * INV_LO + bb[col + 1];
                if constexpr (MODE <= 1) {
                    v0 = silu(v0); v1 = silu(v1);
                    __half* H = (MODE == 0 ? g_Hsh : g_Hrh);
                    *reinterpret_cast<__half2*>(H + (size_t)grow * NDIM + col)
                        = __halves2half2(__float2half(v0), __float2half(v1));
                } else if constexpr (MODE == 2) {
                    *reinterpret_cast<float2*>(out + (size_t)grow * NDIM + col)
                        = make_float2(v0, v1);
                } else {
                    const float w = s_w[m];
                    float* dst = out + (size_t)s_tok[m] * NDIM + col;
                    atomicAdd(dst + 0, w * v0);
                    atomicAdd(dst + 1, w * v1);
                }
            }
        }
    }
}

__global__ void __launch_bounds__(256) gemm_m0(const float* __restrict__ bias) {
    gemm_body<0, D, HD>(bias, nullptr);
}
__global__ void __launch_bounds__(256) gemm_m1(const float* __restrict__ bias) {
    gemm_body<1, D, HD>(bias, nullptr);
}
__global__ void __launch_bounds__(256) gemm_m2(const float* __restrict__ bias,
                                               float* __restrict__ out) {
    gemm_body<2, HD, D>(bias, out);
}
__global__ void __launch_bounds__(256) gemm_m3(const float* __restrict__ bias,
                                               float* __restrict__ out) {
    gemm_body<3, HD, D>(bias, out);
}

extern "C" void kernel_launch(void* const* d_in, const int* in_sizes, int n_in,
                              void* d_out, int out_size) {
    (void)in_sizes; (void)n_in; (void)out_size;
    const float* X   = (const float*)d_in[0];
    const float* RW  = (const float*)d_in[1];
    const float* EB  = (const float*)d_in[2];
    const float* sW1 = (const float*)d_in[3];
    const float* sb1 = (const float*)d_in[4];
    const float* sW2 = (const float*)d_in[5];
    const float* sb2 = (const float*)d_in[6];
    const float* rW1 = (const float*)d_in[7];
    const float* rb1 = (const float*)d_in[8];
    const float* rW2 = (const float*)d_in[9];
    const float* rb2 = (const float*)d_in[10];
    float* out = (float*)d_out;

    init_kernel<<<(CAP + 255) / 256, 256>>>();
    routing_kernel<<<NTOK / 8, 256>>>(X, RW, EB);
    prefix_kernel<<<1, 32>>>();
    scatter_kernel<<<(NTOK * 2) / 256, 256>>>();

    cvt_x_kernel<<<(NTOK * D / 2 + 255) / 256, 256>>>(X, NTOK * D);
    cvt_w_kernel<<<(D * HD / 2 + 255) / 256, 256>>>(sW1, D * HD, 1);
    cvt_w_kernel<<<(HD * D / 2 + 255) / 256, 256>>>(sW2, HD * D, 2);
    cvt_w_kernel<<<(NE * D * HD / 2 + 255) / 256, 256>>>(rW1, NE * D * HD, 3);
    cvt_w_kernel<<<(NE * HD * D / 2 + 255) / 256, 256>>>(rW2, NE * HD * D, 4);

    gemm_m0<<<dim3(HD / BN, NTOK / BM), 256>>>(sb1);
    gemm_m1<<<dim3(HD / BN, CAP / BM), 256>>>(rb1);
    gemm_m2<<<dim3(D / BN, NTOK / BM), 256>>>(sb2, out);
    gemm_m3<<<dim3(D / BN, CAP / BM), 256>>>(rb2, out);
}

// round 11
// speedup vs baseline: 1.8348x; 1.6564x over previous
#include <cuda_runtime.h>
#include <cuda_fp16.h>
#include <cstdint>
#include <math.h>

namespace {
constexpr int NTOK = 8192;
constexpr int D    = 1024;
constexpr int HD   = 512;
constexpr int NE   = 8;
constexpr int BM = 128, BN = 128;
constexpr int CAP  = 17408;            // 2*NTOK + per-expert pad to 128
}

__device__ int   g_counts[NE];
__device__ int   g_offsets[NE + 1];
__device__ int   g_cursor[NE];
__device__ int   g_perm[CAP];
__device__ float g_wgt[CAP];
__device__ int   g_tok_e[NTOK * 2];
__device__ float g_tok_w[NTOK * 2];

// fp16 operands, single plane. Weights [K,N] row-major.
__device__ __align__(16) __half g_Xh[NTOK * D];
__device__ __align__(16) __half g_W1h[D * HD];
__device__ __align__(16) __half g_W2h[HD * D];
__device__ __align__(16) __half g_r1h[NE * D * HD];
__device__ __align__(16) __half g_r2h[NE * HD * D];
__device__ __align__(16) __half g_Hsh[NTOK * HD];
__device__ __align__(16) __half g_Hrh[(size_t)CAP * HD];

// ---------------- routing / bookkeeping ----------------

__global__ void init_kernel() {
    int i = blockIdx.x * blockDim.x + threadIdx.x;
    if (i < NE) g_counts[i] = 0;
    if (i < CAP) { g_perm[i] = 0; g_wgt[i] = 0.0f; }
}

__global__ void routing_kernel(const float* __restrict__ X,
                               const float* __restrict__ RW,
                               const float* __restrict__ EB) {
    int warp = (blockIdx.x * blockDim.x + threadIdx.x) >> 5;
    int lane = threadIdx.x & 31;
    if (warp >= NTOK) return;
    const float* x = X + (size_t)warp * D;
    float acc[NE];
#pragma unroll
    for (int e = 0; e < NE; e++) acc[e] = 0.0f;
    for (int k = lane; k < D; k += 32) {
        float xv = x[k];
#pragma unroll
        for (int e = 0; e < NE; e++) acc[e] = fmaf(xv, RW[e * D + k], acc[e]);
    }
#pragma unroll
    for (int e = 0; e < NE; e++) {
#pragma unroll
        for (int o = 16; o > 0; o >>= 1)
            acc[e] += __shfl_down_sync(0xffffffffu, acc[e], o);
    }
    if (lane == 0) {
        float act[NE];
#pragma unroll
        for (int e = 0; e < NE; e++) {
            float l = acc[e] + EB[e];
            float sp = (l > 0.0f) ? (l + log1pf(expf(-l))) : log1pf(expf(l));
            act[e] = sqrtf(sp);
        }
        int i0 = 0;
#pragma unroll
        for (int e = 1; e < NE; e++) if (act[e] > act[i0]) i0 = e;
        int i1 = (i0 == 0) ? 1 : 0;
#pragma unroll
        for (int e = 0; e < NE; e++)
            if (e != i0 && act[e] > act[i1]) i1 = e;
        g_tok_e[2 * warp + 0] = i0; g_tok_w[2 * warp + 0] = act[i0];
        g_tok_e[2 * warp + 1] = i1; g_tok_w[2 * warp + 1] = act[i1];
        atomicAdd(&g_counts[i0], 1);
        atomicAdd(&g_counts[i1], 1);
    }
}

__global__ void prefix_kernel() {
    if (threadIdx.x == 0 && blockIdx.x == 0) {
        int off = 0;
        for (int e = 0; e < NE; e++) {
            g_offsets[e] = off;
            g_cursor[e]  = off;
            off += ((g_counts[e] + BM - 1) / BM) * BM;
        }
        g_offsets[NE] = off;
    }
}

__global__ void scatter_kernel() {
    int i = blockIdx.x * blockDim.x + threadIdx.x;
    if (i >= NTOK * 2) return;
    int e = g_tok_e[i];
    int slot = atomicAdd(&g_cursor[e], 1);
    g_perm[slot] = i >> 1;
    g_wgt[slot]  = g_tok_w[i];
}

// fp32 -> fp16
__global__ void cvt_kernel(const float* __restrict__ src, int n, int sel) {
    int i = (blockIdx.x * blockDim.x + threadIdx.x) * 2;
    if (i >= n) return;
    float2 v = *reinterpret_cast<const float2*>(src + i);
    __half* p;
    switch (sel) {
        case 0:  p = g_Xh;  break;
        case 1:  p = g_W1h; break;
        case 2:  p = g_W2h; break;
        case 3:  p = g_r1h; break;
        default: p = g_r2h; break;
    }
    *reinterpret_cast<__half2*>(p + i) =
        __halves2half2(__float2half(v.x), __float2half(v.y));
}

__device__ __forceinline__ float silu(float v) { return v / (1.0f + expf(-v)); }

// ---------------- mma helpers ----------------

__device__ __forceinline__ void ldsm4(uint32_t (&r)[4], uint32_t addr) {
    asm volatile("ldmatrix.sync.aligned.m8n8.x4.shared.b16 {%0,%1,%2,%3}, [%4];\n"
        : "=r"(r[0]), "=r"(r[1]), "=r"(r[2]), "=r"(r[3]) : "r"(addr));
}
__device__ __forceinline__ void ldsm4t(uint32_t (&r)[4], uint32_t addr) {
    asm volatile("ldmatrix.sync.aligned.m8n8.x4.trans.shared.b16 {%0,%1,%2,%3}, [%4];\n"
        : "=r"(r[0]), "=r"(r[1]), "=r"(r[2]), "=r"(r[3]) : "r"(addr));
}
__device__ __forceinline__ void mma_f16(float (&c)[4], const uint32_t (&a)[4],
                                        uint32_t b0, uint32_t b1) {
    asm volatile(
        "mma.sync.aligned.m16n8k16.row.col.f32.f16.f16.f32 "
        "{%0,%1,%2,%3}, {%4,%5,%6,%7}, {%8,%9}, {%0,%1,%2,%3};\n"
        : "+f"(c[0]), "+f"(c[1]), "+f"(c[2]), "+f"(c[3])
        : "r"(a[0]), "r"(a[1]), "r"(a[2]), "r"(a[3]), "r"(b0), "r"(b1));
}

// MODE 0: Hs = silu(X@W1+b)      MODE 1: Hr = silu(X[perm]@rW1[e]+b)
// MODE 2: out = Hs@W2+b (store)  MODE 3: out[tok] += w*(Hr@rW2[e]+b) (atomic)
template <int MODE, int KDIM, int NDIM>
__device__ __forceinline__ void gemm_body(const float* __restrict__ bias,
                                          float* __restrict__ out) {
    __shared__ __align__(16) __half sA[2][128][24];    // [stage][m][k]
    __shared__ __align__(16) __half sB[2][16][136];    // [stage][k][n]
    __shared__ int   s_row[128];
    __shared__ int   s_tok[128];
    __shared__ float s_w[128];

    const int tid = threadIdx.x;
    const int rowTile = blockIdx.y * BM;
    const int colTile = blockIdx.x * BN;

    const __half* Wp;
    const float* bb = bias;
    if constexpr (MODE == 0)      Wp = g_W1h;
    else if constexpr (MODE == 2) Wp = g_W2h;
    else {
        int e = 0;
#pragma unroll
        for (int i = 1; i < NE; i++) if (rowTile >= g_offsets[i]) e = i;
        size_t off = (size_t)e * KDIM * NDIM;
        if constexpr (MODE == 1) Wp = g_r1h + off;
        else                     Wp = g_r2h + off;
        bb = bias + e * NDIM;
    }
    const __half* Ag;
    if constexpr (MODE <= 1)      Ag = g_Xh;
    else if constexpr (MODE == 2) Ag = g_Hsh;
    else                          Ag = g_Hrh;

    if (tid < BM) {
        int r = rowTile + tid;
        if constexpr (MODE == 1) s_row[tid] = g_perm[r];
        else                     s_row[tid] = r;
        if constexpr (MODE == 3) { s_tok[tid] = g_perm[r]; s_w[tid] = g_wgt[r]; }
    }
    __syncthreads();

    const int lane = tid & 31, warp = tid >> 5;
    const int wm = warp >> 2;     // 0..1 -> 64 rows each
    const int wn = warp & 3;      // 0..3 -> 32 cols each

    // staging (global->reg->smem)
    const int aR = tid >> 1,  aC = (tid & 1) * 8;
    const int bR = tid >> 4,  bC = (tid & 15) * 8;
    const size_t arow = (size_t)s_row[aR];
    const __half* Ap = Ag + arow * KDIM + aC;
    const __half* Bp = Wp + (size_t)bR * NDIM + colTile + bC;

    // ldmatrix lane addresses
    uint32_t sAaddr = (uint32_t)__cvta_generic_to_shared(
        &sA[0][wm * 64 + (lane & 15)][(lane >> 4) * 8]);
    uint32_t sBaddr = (uint32_t)__cvta_generic_to_shared(
        &sB[0][(lane & 7) + ((lane >> 3) & 1) * 8][wn * 32 + (lane >> 4) * 8]);
    constexpr uint32_t A_STAGE = 128 * 24 * 2;     // 6144
    constexpr uint32_t B_STAGE = 16 * 136 * 2;     // 4352

    float acc[4][4][4] = {};
    uint4 rA, rB;

    // prologue: stage 0
    rA = *reinterpret_cast<const uint4*>(Ap);
    rB = *reinterpret_cast<const uint4*>(Bp);
    *reinterpret_cast<uint4*>(&sA[0][aR][aC]) = rA;
    *reinterpret_cast<uint4*>(&sB[0][bR][bC]) = rB;
    __syncthreads();

    int st = 0;
    for (int kt = 0; kt < KDIM; kt += 16) {
        const bool more = (kt + 16 < KDIM);
        if (more) {
            rA = *reinterpret_cast<const uint4*>(Ap + kt + 16);
            rB = *reinterpret_cast<const uint4*>(Bp + (size_t)(kt + 16) * NDIM);
        }
        uint32_t aF[4][4], bF[2][4];
#pragma unroll
        for (int mi = 0; mi < 4; mi++)
            ldsm4(aF[mi], sAaddr + st * A_STAGE + mi * (16 * 24 * 2));
#pragma unroll
        for (int p = 0; p < 2; p++)
            ldsm4t(bF[p], sBaddr + st * B_STAGE + p * (16 * 2));
#pragma unroll
        for (int mi = 0; mi < 4; mi++)
#pragma unroll
            for (int ni = 0; ni < 4; ni++) {
                const int p = ni >> 1, q = (ni & 1) * 2;
                mma_f16(acc[mi][ni], aF[mi], bF[p][q], bF[p][q + 1]);
            }
        if (more) {
            *reinterpret_cast<uint4*>(&sA[st ^ 1][aR][aC]) = rA;
            *reinterpret_cast<uint4*>(&sB[st ^ 1][bR][bC]) = rB;
        }
        st ^= 1;
        __syncthreads();
    }

    // epilogue
    const int r0 = lane >> 2, c0 = (lane & 3) * 2;
#pragma unroll
    for (int mi = 0; mi < 4; mi++) {
#pragma unroll
        for (int rr = 0; rr < 2; rr++) {
            const int m = wm * 64 + mi * 16 + r0 + rr * 8;
            const int grow = rowTile + m;
#pragma unroll
            for (int ni = 0; ni < 4; ni++) {
                const int col = colTile + wn * 32 + ni * 8 + c0;
                float v0 = acc[mi][ni][rr * 2 + 0] + bb[col];
                float v1 = acc[mi][ni][rr * 2 + 1] + bb[col + 1];
                if constexpr (MODE <= 1) {
                    v0 = silu(v0); v1 = silu(v1);
                    __half* H = (MODE == 0 ? g_Hsh : g_Hrh);
                    *reinterpret_cast<__half2*>(H + (size_t)grow * NDIM + col)
                        = __halves2half2(__float2half(v0), __float2half(v1));
                } else if constexpr (MODE == 2) {
                    *reinterpret_cast<float2*>(out + (size_t)grow * NDIM + col)
                        = make_float2(v0, v1);
                } else {
                    const float w = s_w[m];
                    float* dst = out + (size_t)s_tok[m] * NDIM + col;
                    atomicAdd(dst + 0, w * v0);
                    atomicAdd(dst + 1, w * v1);
                }
            }
        }
    }
}

__global__ void __launch_bounds__(256, 2) gemm_m0(const float* __restrict__ bias) {
    gemm_body<0, D, HD>(bias, nullptr);
}
__global__ void __launch_bounds__(256, 2) gemm_m1(const float* __restrict__ bias) {
    gemm_body<1, D, HD>(bias, nullptr);
}
__global__ void __launch_bounds__(256, 2) gemm_m2(const float* __restrict__ bias,
                                                  float* __restrict__ out) {
    gemm_body<2, HD, D>(bias, out);
}
__global__ void __launch_bounds__(256, 2) gemm_m3(const float* __restrict__ bias,
                                                  float* __restrict__ out) {
    gemm_body<3, HD, D>(bias, out);
}

extern "C" void kernel_launch(void* const* d_in, const int* in_sizes, int n_in,
                              void* d_out, int out_size) {
    (void)in_sizes; (void)n_in; (void)out_size;
    const float* X   = (const float*)d_in[0];
    const float* RW  = (const float*)d_in[1];
    const float* EB  = (const float*)d_in[2];
    const float* sW1 = (const float*)d_in[3];
    const float* sb1 = (const float*)d_in[4];
    const float* sW2 = (const float*)d_in[5];
    const float* sb2 = (const float*)d_in[6];
    const float* rW1 = (const float*)d_in[7];
    const float* rb1 = (const float*)d_in[8];
    const float* rW2 = (const float*)d_in[9];
    const float* rb2 = (const float*)d_in[10];
    float* out = (float*)d_out;

    init_kernel<<<(CAP + 255) / 256, 256>>>();
    routing_kernel<<<NTOK / 8, 256>>>(X, RW, EB);
    prefix_kernel<<<1, 32>>>();
    scatter_kernel<<<(NTOK * 2) / 256, 256>>>();

    cvt_kernel<<<(NTOK * D / 2 + 255) / 256, 256>>>(X, NTOK * D, 0);
    cvt_kernel<<<(D * HD / 2 + 255) / 256, 256>>>(sW1, D * HD, 1);
    cvt_kernel<<<(HD * D / 2 + 255) / 256, 256>>>(sW2, HD * D, 2);
    cvt_kernel<<<(NE * D * HD / 2 + 255) / 256, 256>>>(rW1, NE * D * HD, 3);
    cvt_kernel<<<(NE * HD * D / 2 + 255) / 256, 256>>>(rW2, NE * HD * D, 4);

    gemm_m0<<<dim3(HD / BN, NTOK / BM), 256>>>(sb1);
    gemm_m1<<<dim3(HD / BN, CAP / BM), 256>>>(rb1);
    gemm_m2<<<dim3(D / BN, NTOK / BM), 256>>>(sb2, out);
    gemm_m3<<<dim3(D / BN, CAP / BM), 256>>>(rb2, out);
}